// round 2
// baseline (speedup 1.0000x reference)
#include <cuda_runtime.h>
#include <math.h>
#include <stdint.h>

#define B_    128
#define S_    128
#define E_    512
#define HID_  1024
#define NH_   16
#define DH_   64
#define V_    8192
#define IN_   1536
#define G3_   3072
#define BS_   (B_*S_)   // 16384

// ---------------- scratch (device globals; no allocation allowed) ----------------
__device__ float g_combined[(size_t)BS_*IN_];   // [B,S,IN]: [:,:,0:512]=embedded, [:,:,512:]=context
__device__ float g_q[(size_t)B_*HID_];
__device__ float g_k[(size_t)BS_*HID_];
__device__ float g_v[(size_t)BS_*HID_];
__device__ float g_ctxpre[(size_t)BS_*HID_];    // scrambled attention out, pre-Wo
__device__ float g_gi0[(size_t)BS_*G3_];        // x@Wih0^T + bih0, rows indexed (b*S+t)
__device__ float g_h0[(size_t)B_*HID_];
__device__ float g_h1[(size_t)B_*HID_];
__device__ float g_gh0[(size_t)B_*G3_];
__device__ float g_gh1[(size_t)B_*G3_];
__device__ float g_gi1[(size_t)B_*G3_];
__device__ float g_rnn[(size_t)BS_*HID_];       // rnn_out [B,S,HID]
__device__ float g_lin1[(size_t)BS_*HID_];      // W1 out
__device__ float g_act[(size_t)BS_*HID_];       // elu(layernorm(..))

// ---------------- generic SIMT GEMM: C[m,n] = sum_k A[m,k] * W[n,k] + bias[n] ----
// A optionally split at column ksplit into a second matrix A2 (for the concat GEMM).
template<int BM, int BN, int BK, int TM, int TN>
__device__ __forceinline__ void gemm_body(
    float* sm,
    const float* __restrict__ A, int lda,
    const float* __restrict__ A2, int ksplit, int lda2,
    const float* __restrict__ W, int ldw,
    const float* __restrict__ bias,
    float* __restrict__ C, int ldc,
    int M, int N, int K)
{
    constexpr int BNT = BN / TN;
    constexpr int KV  = BK / 4;
    float* As = sm;                 // [2][BK][BM]
    float* Bs = sm + 2 * BK * BM;   // [2][BK][BN]

    const int tid = threadIdx.x;
    const int bm  = blockIdx.y * BM;
    const int bn  = blockIdx.x * BN;

    const int ar = tid / KV;          // row within tile (A) / n within tile (B)
    const int ak = (tid % KV) * 4;    // k offset within chunk

    const int col0 = (tid % BNT) * TN;
    const int row0 = (tid / BNT) * TM;

    const float* wbase = W + (size_t)(bn + ar) * ldw + ak;

    float acc[TM][TN];
#pragma unroll
    for (int i = 0; i < TM; ++i)
#pragma unroll
        for (int j = 0; j < TN; ++j) acc[i][j] = 0.f;

    // chunk-0 load
    {
        const float* ap;
        if (A2 != nullptr && 0 >= ksplit)
            ap = A2 + (size_t)(bm + ar) * lda2 + (0 - ksplit) + ak;
        else
            ap = A + (size_t)(bm + ar) * lda + 0 + ak;
        float4 av = *(const float4*)ap;
        float4 bv = *(const float4*)wbase;
        float* dA = As + ak * BM + ar;
        dA[0] = av.x; dA[BM] = av.y; dA[2 * BM] = av.z; dA[3 * BM] = av.w;
        float* dB = Bs + ak * BN + ar;
        dB[0] = bv.x; dB[BN] = bv.y; dB[2 * BN] = bv.z; dB[3 * BN] = bv.w;
    }
    __syncthreads();

    const int nk = K / BK;
    for (int c = 0; c < nk; ++c) {
        const int cur = c & 1, nxt = cur ^ 1;
        float4 pav, pbv;
        const bool has = (c + 1 < nk);
        if (has) {
            const int k0 = (c + 1) * BK;
            const float* ap;
            if (A2 != nullptr && k0 >= ksplit)
                ap = A2 + (size_t)(bm + ar) * lda2 + (k0 - ksplit) + ak;
            else
                ap = A + (size_t)(bm + ar) * lda + k0 + ak;
            pav = *(const float4*)ap;
            pbv = *(const float4*)(wbase + k0);
        }
        const float* Acur = As + cur * BK * BM;
        const float* Bcur = Bs + cur * BK * BN;
#pragma unroll
        for (int kk = 0; kk < BK; ++kk) {
            float af[TM], bf[TN];
#pragma unroll
            for (int i = 0; i < TM; i += 4) {
                float4 t = *(const float4*)(Acur + kk * BM + row0 + i);
                af[i] = t.x; af[i + 1] = t.y; af[i + 2] = t.z; af[i + 3] = t.w;
            }
#pragma unroll
            for (int j = 0; j < TN; j += 4) {
                float4 t = *(const float4*)(Bcur + kk * BN + col0 + j);
                bf[j] = t.x; bf[j + 1] = t.y; bf[j + 2] = t.z; bf[j + 3] = t.w;
            }
#pragma unroll
            for (int i = 0; i < TM; ++i)
#pragma unroll
                for (int j = 0; j < TN; ++j) acc[i][j] += af[i] * bf[j];
        }
        if (has) {
            float* dA = As + nxt * BK * BM + ak * BM + ar;
            dA[0] = pav.x; dA[BM] = pav.y; dA[2 * BM] = pav.z; dA[3 * BM] = pav.w;
            float* dB = Bs + nxt * BK * BN + ak * BN + ar;
            dB[0] = pbv.x; dB[BN] = pbv.y; dB[2 * BN] = pbv.z; dB[3 * BN] = pbv.w;
        }
        __syncthreads();
    }

#pragma unroll
    for (int i = 0; i < TM; ++i) {
        float* cp = C + (size_t)(bm + row0 + i) * ldc + bn + col0;
#pragma unroll
        for (int j = 0; j < TN; j += 4) {
            float4 o;
            o.x = acc[i][j + 0] + bias[bn + col0 + j + 0];
            o.y = acc[i][j + 1] + bias[bn + col0 + j + 1];
            o.z = acc[i][j + 2] + bias[bn + col0 + j + 2];
            o.w = acc[i][j + 3] + bias[bn + col0 + j + 3];
            *(float4*)(cp + j) = o;
        }
    }
}

__global__ __launch_bounds__(256) void sgemm_big_kernel(
    const float* A, int lda, const float* A2, int ksplit, int lda2,
    const float* W, int ldw, const float* bias, float* C, int ldc,
    int M, int N, int K)
{
    extern __shared__ float sm[];
    gemm_body<128, 128, 8, 8, 8>(sm, A, lda, A2, ksplit, lda2, W, ldw, bias, C, ldc, M, N, K);
}

__global__ __launch_bounds__(256) void sgemm_small_kernel(
    const float* A, int lda, const float* A2, int ksplit, int lda2,
    const float* W, int ldw, const float* bias, float* C, int ldc,
    int M, int N, int K)
{
    extern __shared__ float sm[];
    gemm_body<64, 64, 16, 4, 4>(sm, A, lda, A2, ksplit, lda2, W, ldw, bias, C, ldc, M, N, K);
}

// both recurrent h-GEMMs of a step in one launch (z dispatch), to fill the chip
__global__ __launch_bounds__(256) void gru_phase1_kernel(
    const float* h0, const float* Whh0, const float* bhh0, float* gh0,
    const float* h1, const float* Whh1, const float* bhh1, float* gh1)
{
    extern __shared__ float sm[];
    if (blockIdx.z == 0)
        gemm_body<64, 64, 16, 4, 4>(sm, h0, HID_, nullptr, 1 << 30, 0, Whh0, HID_, bhh0, gh0, G3_, B_, G3_, HID_);
    else
        gemm_body<64, 64, 16, 4, 4>(sm, h1, HID_, nullptr, 1 << 30, 0, Whh1, HID_, bhh1, gh1, G3_, B_, G3_, HID_);
}

static const int GEMM_SMEM = 2 * (8 * 128 + 8 * 128) * 4;  // == 16384 for both configs

// ---------------- embedding + positional encoding ----------------
// NOTE: faithful to the reference broadcast: embedded[b,s,e] = emb[x[b,s],e] + pe[b,0,e]
__global__ void embed_kernel(const int* __restrict__ x, const float* __restrict__ emb,
                             const float* __restrict__ pe, float* __restrict__ combined)
{
    int idx = blockIdx.x * 256 + threadIdx.x;      // over B*S*E
    if (idx >= BS_ * E_) return;
    int e  = idx & (E_ - 1);
    int bs = idx >> 9;                              // E_=512
    int b  = bs >> 7;                               // S_=128
    combined[(size_t)bs * IN_ + e] = emb[(size_t)x[bs] * E_ + e] + pe[(size_t)b * E_ + e];
}

// ---------------- attention core: one block per (b,s) ----------------
__global__ __launch_bounds__(256) void attn_kernel(
    const float* __restrict__ q, const float* __restrict__ k, const float* __restrict__ v,
    const float* __restrict__ score_w, float* __restrict__ attn_out, float* __restrict__ ctxpre)
{
    int bs = blockIdx.x;
    int b = bs >> 7, s = bs & 127;
    __shared__ float qs[NH_][DH_];
    __shared__ float ks[NH_][DH_ + 1];
    __shared__ float vs[NH_][DH_ + 1];
    __shared__ float sq[NH_], sk[NH_];
    __shared__ float scs[NH_][NH_ + 1];
    __shared__ float es[NH_][NH_ + 1];

    int tid = threadIdx.x;
    const float* qp = q + (size_t)b * HID_;
    const float* kp = k + (size_t)bs * HID_;
    const float* vp = v + (size_t)bs * HID_;
    for (int i = tid; i < HID_; i += 256) {
        qs[i >> 6][i & 63] = qp[i];
        ks[i >> 6][i & 63] = kp[i];
        vs[i >> 6][i & 63] = vp[i];
    }
    __syncthreads();

    if (tid < 32) {
        int h = tid & 15;
        bool isq = tid < 16;
        float ssum = 0.f;
        for (int d = 0; d < DH_; ++d) { float xv = isq ? qs[h][d] : ks[h][d]; ssum += xv * xv; }
        if (isq) sq[h] = ssum; else sk[h] = ssum;
    }

    int i = tid >> 4, j = tid & 15;
    float num = 0.f;
    for (int d = 0; d < DH_; ++d) num += qs[i][d] * ks[j][d];
    __syncthreads();   // sq/sk ready

    float w0, w1, w2;
    {
        float a = score_w[0], bb = score_w[1], c = score_w[2];
        float mx = fmaxf(a, fmaxf(bb, c));
        float ea = expf(a - mx), eb = expf(bb - mx), ec = expf(c - mx);
        float sm3 = ea + eb + ec;
        w0 = ea / sm3; w1 = eb / sm3; w2 = ec / sm3;
    }

    float dot = num * 0.125f;                                    // 1/sqrt(64)
    float denom = fmaxf(sqrtf(sq[i]) * sqrtf(sk[j]), 1e-8f);
    float cosv = num / denom;
    float d2 = sq[i] + sk[j] - 2.f * num;
    float dist = -sqrtf(fmaxf(d2, 0.f));
    float sc = w0 * dot + w1 * cosv + w2 * dist;
    scs[i][j] = sc;
    __syncthreads();

    float mx = scs[i][0];
#pragma unroll
    for (int jj = 1; jj < NH_; ++jj) mx = fmaxf(mx, scs[i][jj]);
    float ev = expf(sc - mx);
    es[i][j] = ev;
    __syncthreads();

    float ssum = 0.f;
#pragma unroll
    for (int jj = 0; jj < NH_; ++jj) ssum += es[i][jj];
    float a = ev / ssum;
    attn_out[((size_t)bs * NH_ + i) * NH_ + j] = a;
    scs[i][j] = a;                 // reuse as attention matrix
    __syncthreads();

    // out[i][d] = sum_j attn[i][j] * v[j][d]; thread -> (i2, 4 d's)
    int i2 = tid >> 4;
    int d0 = (tid & 15) * 4;
    float o0 = 0.f, o1 = 0.f, o2 = 0.f, o3 = 0.f;
#pragma unroll
    for (int jj = 0; jj < NH_; ++jj) {
        float aij = scs[i2][jj];
        o0 += aij * vs[jj][d0 + 0];
        o1 += aij * vs[jj][d0 + 1];
        o2 += aij * vs[jj][d0 + 2];
        o3 += aij * vs[jj][d0 + 3];
    }
    // scrambled layout from torch transpose(1,2).view: ctx[b, i*8 + s/16, (s%16)*64 + d]
    int m = i2 * 8 + (s >> 4);
    size_t cbase = ((size_t)(b * 128 + m)) * HID_ + (size_t)(s & 15) * 64 + d0;
    ctxpre[cbase + 0] = o0; ctxpre[cbase + 1] = o1;
    ctxpre[cbase + 2] = o2; ctxpre[cbase + 3] = o3;
}

// ---------------- GRU elementwise gates ----------------
__device__ __forceinline__ float sigm(float x) { return 1.f / (1.f + expf(-x)); }

__global__ void gru_ew0(const float* __restrict__ gi0, const float* __restrict__ gh0,
                        float* __restrict__ h0, int t)
{
    int idx = blockIdx.x * 256 + threadIdx.x;   // B*HID
    int b = idx >> 10, j = idx & 1023;
    const float* gi = gi0 + (size_t)(b * S_ + t) * G3_;
    const float* gh = gh0 + (size_t)b * G3_;
    float r = sigm(gi[j] + gh[j]);
    float z = sigm(gi[HID_ + j] + gh[HID_ + j]);
    float n = tanhf(gi[2 * HID_ + j] + r * gh[2 * HID_ + j]);
    float h = h0[idx];
    h0[idx] = (1.f - z) * n + z * h;
}

__global__ void gru_ew1(const float* __restrict__ gi1, const float* __restrict__ gh1,
                        float* __restrict__ h1, float* __restrict__ rnn, int t)
{
    int idx = blockIdx.x * 256 + threadIdx.x;
    int b = idx >> 10, j = idx & 1023;
    const float* gi = gi1 + (size_t)b * G3_;
    const float* gh = gh1 + (size_t)b * G3_;
    float r = sigm(gi[j] + gh[j]);
    float z = sigm(gi[HID_ + j] + gh[HID_ + j]);
    float n = tanhf(gi[2 * HID_ + j] + r * gh[2 * HID_ + j]);
    float hn = (1.f - z) * n + z * h1[idx];
    h1[idx] = hn;
    rnn[(size_t)(b * S_ + t) * HID_ + j] = hn;
}

// ---------------- LayerNorm + ELU (one block per row) ----------------
__global__ __launch_bounds__(256) void ln_elu_kernel(
    const float* __restrict__ hin, const float* __restrict__ gam,
    const float* __restrict__ bet, float* __restrict__ outp)
{
    __shared__ float red[256];
    int row = blockIdx.x;
    const float* p = hin + (size_t)row * HID_;
    int t = threadIdx.x;
    float v[4];
#pragma unroll
    for (int u = 0; u < 4; ++u) v[u] = p[t + u * 256];
    float s = v[0] + v[1] + v[2] + v[3];
    red[t] = s; __syncthreads();
    for (int off = 128; off > 0; off >>= 1) { if (t < off) red[t] += red[t + off]; __syncthreads(); }
    float mean = red[0] * (1.f / HID_);
    __syncthreads();
    float sq = 0.f;
#pragma unroll
    for (int u = 0; u < 4; ++u) { float d = v[u] - mean; sq += d * d; }
    red[t] = sq; __syncthreads();
    for (int off = 128; off > 0; off >>= 1) { if (t < off) red[t] += red[t + off]; __syncthreads(); }
    float var = red[0] * (1.f / HID_);
    float inv = rsqrtf(var + 1e-5f);
#pragma unroll
    for (int u = 0; u < 4; ++u) {
        int c = t + u * 256;
        float y = (v[u] - mean) * inv * gam[c] + bet[c];
        outp[(size_t)row * HID_ + c] = (y > 0.f) ? y : expm1f(y);
    }
}

// ---------------- launch ----------------
extern "C" void kernel_launch(void* const* d_in, const int* in_sizes, int n_in,
                              void* d_out, int out_size)
{
    const int*   x      = (const int*)  d_in[0];
    const float* memory = (const float*)d_in[1];
    const float* hidden = (const float*)d_in[2];
    const float* pe     = (const float*)d_in[3];
    const float* emb    = (const float*)d_in[4];
    const float* Wq = (const float*)d_in[5];  const float* bq = (const float*)d_in[6];
    const float* Wk = (const float*)d_in[7];  const float* bk = (const float*)d_in[8];
    const float* Wv = (const float*)d_in[9];  const float* bv = (const float*)d_in[10];
    const float* Wo = (const float*)d_in[11]; const float* bo = (const float*)d_in[12];
    const float* score_w = (const float*)d_in[13];
    const float* Wih0 = (const float*)d_in[14]; const float* Whh0 = (const float*)d_in[15];
    const float* bih0 = (const float*)d_in[16]; const float* bhh0 = (const float*)d_in[17];
    const float* Wih1 = (const float*)d_in[18]; const float* Whh1 = (const float*)d_in[19];
    const float* bih1 = (const float*)d_in[20]; const float* bhh1 = (const float*)d_in[21];
    const float* W1 = (const float*)d_in[22];   const float* b1 = (const float*)d_in[23];
    const float* ln_g = (const float*)d_in[24]; const float* ln_b = (const float*)d_in[25];
    const float* W2 = (const float*)d_in[26];   const float* b2 = (const float*)d_in[27];

    float* out        = (float*)d_out;
    float* out_logits = out;
    float* out_attn   = out + (size_t)BS_ * V_;
    float* out_hidden = out_attn + (size_t)BS_ * NH_ * NH_;

    float *combined, *qb, *kb, *vb, *ctxpre, *gi0, *h0, *h1, *gh0, *gh1, *gi1, *rnn, *lin1, *act;
    cudaGetSymbolAddress((void**)&combined, g_combined);
    cudaGetSymbolAddress((void**)&qb, g_q);
    cudaGetSymbolAddress((void**)&kb, g_k);
    cudaGetSymbolAddress((void**)&vb, g_v);
    cudaGetSymbolAddress((void**)&ctxpre, g_ctxpre);
    cudaGetSymbolAddress((void**)&gi0, g_gi0);
    cudaGetSymbolAddress((void**)&h0, g_h0);
    cudaGetSymbolAddress((void**)&h1, g_h1);
    cudaGetSymbolAddress((void**)&gh0, g_gh0);
    cudaGetSymbolAddress((void**)&gh1, g_gh1);
    cudaGetSymbolAddress((void**)&gi1, g_gi1);
    cudaGetSymbolAddress((void**)&rnn, g_rnn);
    cudaGetSymbolAddress((void**)&lin1, g_lin1);
    cudaGetSymbolAddress((void**)&act, g_act);

    const int NOK = 1 << 30;  // "no split" sentinel

    // 1) embedded -> combined[:, :, 0:512]
    embed_kernel<<<(BS_ * E_ + 255) / 256, 256>>>(x, emb, pe, combined);

    // 2) q = hidden[1] @ Wq^T + bq
    sgemm_small_kernel<<<dim3(HID_ / 64, B_ / 64), 256, GEMM_SMEM>>>(
        hidden + (size_t)B_ * HID_, HID_, nullptr, NOK, 0, Wq, HID_, bq, qb, HID_, B_, HID_, HID_);

    // 3) k, v projections
    sgemm_big_kernel<<<dim3(HID_ / 128, BS_ / 128), 256, GEMM_SMEM>>>(
        memory, HID_, nullptr, NOK, 0, Wk, HID_, bk, kb, HID_, BS_, HID_, HID_);
    sgemm_big_kernel<<<dim3(HID_ / 128, BS_ / 128), 256, GEMM_SMEM>>>(
        memory, HID_, nullptr, NOK, 0, Wv, HID_, bv, vb, HID_, BS_, HID_, HID_);

    // 4) attention core (also writes attn_w output)
    attn_kernel<<<BS_, 256>>>(qb, kb, vb, score_w, out_attn, ctxpre);

    // 5) context = ctxpre @ Wo^T + bo  -> combined[:, :, 512:1536]
    sgemm_big_kernel<<<dim3(HID_ / 128, BS_ / 128), 256, GEMM_SMEM>>>(
        ctxpre, HID_, nullptr, NOK, 0, Wo, HID_, bo, combined + E_, IN_, BS_, HID_, HID_);

    // 6) gi0 = combined @ Wih0^T + bih0  (rows b*S+t)
    sgemm_big_kernel<<<dim3(G3_ / 128, BS_ / 128), 256, GEMM_SMEM>>>(
        combined, IN_, nullptr, NOK, 0, Wih0, IN_, bih0, gi0, G3_, BS_, G3_, IN_);

    // 7) init GRU states
    cudaMemcpyToSymbolAsync(g_h0, hidden, (size_t)B_ * HID_ * sizeof(float), 0,
                            cudaMemcpyDeviceToDevice, 0);
    cudaMemcpyToSymbolAsync(g_h1, hidden + (size_t)B_ * HID_, (size_t)B_ * HID_ * sizeof(float), 0,
                            cudaMemcpyDeviceToDevice, 0);

    // 8) GRU recurrence
    for (int t = 0; t < S_; ++t) {
        gru_phase1_kernel<<<dim3(G3_ / 64, B_ / 64, 2), 256, GEMM_SMEM>>>(
            h0, Whh0, bhh0, gh0, h1, Whh1, bhh1, gh1);
        gru_ew0<<<(B_ * HID_) / 256, 256>>>(gi0, gh0, h0, t);
        sgemm_small_kernel<<<dim3(G3_ / 64, B_ / 64), 256, GEMM_SMEM>>>(
            h0, HID_, nullptr, NOK, 0, Wih1, HID_, bih1, gi1, G3_, B_, G3_, HID_);
        gru_ew1<<<(B_ * HID_) / 256, 256>>>(gi1, gh1, h1, rnn, t);
    }

    // 9) new_hidden output
    cudaMemcpyFromSymbolAsync(out_hidden, g_h0, (size_t)B_ * HID_ * sizeof(float), 0,
                              cudaMemcpyDeviceToDevice, 0);
    cudaMemcpyFromSymbolAsync(out_hidden + (size_t)B_ * HID_, g_h1,
                              (size_t)B_ * HID_ * sizeof(float), 0, cudaMemcpyDeviceToDevice, 0);

    // 10) h = concat(rnn_out, context) @ W1^T + b1   (A2 = context slice of combined)
    sgemm_big_kernel<<<dim3(HID_ / 128, BS_ / 128), 256, GEMM_SMEM>>>(
        rnn, HID_, combined + E_, HID_, IN_, W1, 2 * HID_, b1, lin1, HID_, BS_, HID_, 2 * HID_);

    // 11) LayerNorm + ELU
    ln_elu_kernel<<<BS_, 256>>>(lin1, ln_g, ln_b, act);

    // 12) logits = act @ W2^T + b2
    sgemm_big_kernel<<<dim3(V_ / 128, BS_ / 128), 256, GEMM_SMEM>>>(
        act, HID_, nullptr, NOK, 0, W2, HID_, b2, out_logits, V_, BS_, V_, HID_);
}

// round 6
// speedup vs baseline: 3.1228x; 3.1228x over previous
#include <cuda_runtime.h>
#include <math.h>
#include <stdint.h>

#define B_    128
#define S_    128
#define E_    512
#define HID_  1024
#define NH_   16
#define DH_   64
#define V_    8192
#define IN_   1536
#define G3_   3072
#define BS_   (B_*S_)   // 16384

// ---------------- scratch (device globals; no allocation allowed) ----------------
__device__ float g_combined[(size_t)BS_*IN_];
__device__ float g_q[(size_t)B_*HID_];
__device__ float g_k[(size_t)BS_*HID_];
__device__ float g_v[(size_t)BS_*HID_];
__device__ float g_ctxpre[(size_t)BS_*HID_];
__device__ float g_gi0[(size_t)BS_*G3_];
__device__ float g_h0[(size_t)B_*HID_];
__device__ float g_h1[(size_t)B_*HID_];
__device__ float g_gh0[(size_t)B_*G3_];
__device__ float g_gh1[(size_t)B_*G3_];
__device__ float g_gi1[(size_t)B_*G3_];
__device__ float g_rnn[(size_t)BS_*HID_];
__device__ float g_lin1[(size_t)BS_*HID_];
__device__ float g_act[(size_t)BS_*HID_];

// ================= tf32 tensor-core GEMM =================
// C[m,n] = sum_k A[m,k] * W[n,k] + bias[n]; A optionally split at column ksplit into A2.
// mma.sync.aligned.m16n8k8.row.col.f32.tf32.tf32.f32

__device__ __forceinline__ void cp16(uint32_t s, const void* g) {
    asm volatile("cp.async.cg.shared.global [%0], [%1], 16;" :: "r"(s), "l"(g));
}
__device__ __forceinline__ void cp_commit() { asm volatile("cp.async.commit_group;"); }
template<int N> __device__ __forceinline__ void cp_wait() {
    asm volatile("cp.async.wait_group %0;" :: "n"(N));
}
__device__ __forceinline__ uint32_t f2tf32(float x) {
    uint32_t r; asm("cvt.rna.tf32.f32 %0, %1;" : "=r"(r) : "f"(x)); return r;
}
__device__ __forceinline__ void mma_tf32(float* c, const uint32_t* a, const uint32_t* b) {
    asm volatile("mma.sync.aligned.m16n8k8.row.col.f32.tf32.tf32.f32 "
                 "{%0,%1,%2,%3}, {%4,%5,%6,%7}, {%8,%9}, {%0,%1,%2,%3};"
                 : "+f"(c[0]), "+f"(c[1]), "+f"(c[2]), "+f"(c[3])
                 : "r"(a[0]), "r"(a[1]), "r"(a[2]), "r"(a[3]), "r"(b[0]), "r"(b[1]));
}

#define BK_   32
#define LDS_  36   // BK + 4 pad; conflict-free fragment loads

template<int BM, int BN, int WM, int WN, int STAGES>
__device__ __forceinline__ void tf32_gemm_body(
    const float* __restrict__ A, int lda,
    const float* __restrict__ A2, int ksplit, int lda2,
    const float* __restrict__ W, int ldw,
    const float* __restrict__ bias,
    float* __restrict__ C, int ldc, int K,
    int bxi, int byi)
{
    extern __shared__ float sm[];
    constexpr int THREADS = WM * WN * 32;
    constexpr int WTM = BM / WM;
    constexpr int WTN = BN / WN;
    constexpr int MT  = WTM / 16;
    constexpr int NT  = WTN / 8;

    float* As = sm;                        // [STAGES][BM*LDS_]
    float* Bs = sm + (size_t)STAGES * BM * LDS_;

    const int tid = threadIdx.x;
    const int bm = byi * BM;
    const int bn = bxi * BN;

    const int warp = tid >> 5, lane = tid & 31;
    const int wm = warp / WN, wn = warp % WN;
    const int g = lane >> 2, tg = lane & 3;

    float acc[MT][NT][4];
#pragma unroll
    for (int i = 0; i < MT; ++i)
#pragma unroll
        for (int j = 0; j < NT; ++j) {
            acc[i][j][0] = 0.f; acc[i][j][1] = 0.f; acc[i][j][2] = 0.f; acc[i][j][3] = 0.f;
        }

    auto load_stage = [&](int stage, int k0) {
        const float* Ab; int alda, koff;
        if (A2 != nullptr && k0 >= ksplit) { Ab = A2; alda = lda2; koff = k0 - ksplit; }
        else { Ab = A; alda = lda; koff = k0; }
        constexpr int A4 = BM * 8;     // float4 count per A stage
#pragma unroll
        for (int i = tid; i < A4; i += THREADS) {
            int row = i >> 3, c4 = (i & 7) * 4;
            const float* gp = Ab + (size_t)(bm + row) * alda + koff + c4;
            uint32_t s = (uint32_t)__cvta_generic_to_shared(As + (size_t)stage * BM * LDS_ + row * LDS_ + c4);
            cp16(s, gp);
        }
        constexpr int B4 = BN * 8;
#pragma unroll
        for (int i = tid; i < B4; i += THREADS) {
            int row = i >> 3, c4 = (i & 7) * 4;
            const float* gp = W + (size_t)(bn + row) * ldw + k0 + c4;
            uint32_t s = (uint32_t)__cvta_generic_to_shared(Bs + (size_t)stage * BN * LDS_ + row * LDS_ + c4);
            cp16(s, gp);
        }
        cp_commit();
    };

    const int nk = K / BK_;
#pragma unroll
    for (int s = 0; s < STAGES - 1; ++s) load_stage(s, s * BK_);

    for (int c = 0; c < nk; ++c) {
        cp_wait<STAGES - 2>();
        __syncthreads();
        if (c + STAGES - 1 < nk) load_stage((c + STAGES - 1) % STAGES, (c + STAGES - 1) * BK_);
        else cp_commit();   // empty group keeps wait_group accounting correct

        const float* Ap = As + (size_t)(c % STAGES) * BM * LDS_;
        const float* Bp = Bs + (size_t)(c % STAGES) * BN * LDS_;
#pragma unroll
        for (int kk = 0; kk < BK_ / 8; ++kk) {
            const int k8 = kk * 8;
            uint32_t ua[MT][4], ub[NT][2];
#pragma unroll
            for (int mt = 0; mt < MT; ++mt) {
                int r0 = wm * WTM + mt * 16 + g;
                ua[mt][0] = f2tf32(Ap[r0 * LDS_ + k8 + tg]);
                ua[mt][1] = f2tf32(Ap[(r0 + 8) * LDS_ + k8 + tg]);
                ua[mt][2] = f2tf32(Ap[r0 * LDS_ + k8 + tg + 4]);
                ua[mt][3] = f2tf32(Ap[(r0 + 8) * LDS_ + k8 + tg + 4]);
            }
#pragma unroll
            for (int nt = 0; nt < NT; ++nt) {
                int c0 = wn * WTN + nt * 8 + g;
                ub[nt][0] = f2tf32(Bp[c0 * LDS_ + k8 + tg]);
                ub[nt][1] = f2tf32(Bp[c0 * LDS_ + k8 + tg + 4]);
            }
#pragma unroll
            for (int mt = 0; mt < MT; ++mt)
#pragma unroll
                for (int nt = 0; nt < NT; ++nt)
                    mma_tf32(acc[mt][nt], ua[mt], ub[nt]);
        }
    }

    // epilogue
#pragma unroll
    for (int mt = 0; mt < MT; ++mt) {
        int row0 = bm + wm * WTM + mt * 16 + g;
#pragma unroll
        for (int nt = 0; nt < NT; ++nt) {
            int col = bn + wn * WTN + nt * 8 + 2 * tg;
            float b0 = bias[col], b1 = bias[col + 1];
            float2 v0 = make_float2(acc[mt][nt][0] + b0, acc[mt][nt][1] + b1);
            float2 v1 = make_float2(acc[mt][nt][2] + b0, acc[mt][nt][3] + b1);
            *(float2*)(C + (size_t)row0 * ldc + col) = v0;
            *(float2*)(C + (size_t)(row0 + 8) * ldc + col) = v1;
        }
    }
}

// big: 128x128 tiles, 8 warps (2x4), 3 stages. smem = 3*(128+128)*36*4 = 110592 B
__global__ __launch_bounds__(256, 2) void tf32_gemm_big(
    const float* A, int lda, const float* A2, int ksplit, int lda2,
    const float* W, int ldw, const float* bias, float* C, int ldc, int K)
{
    tf32_gemm_body<128, 128, 2, 4, 3>(A, lda, A2, ksplit, lda2, W, ldw, bias, C, ldc, K,
                                      blockIdx.x, blockIdx.y);
}

// small: 64x64 tiles, 4 warps (2x2), 3 stages. smem = 3*(64+64)*36*4 = 55296 B
__global__ __launch_bounds__(128, 4) void tf32_gemm_small(
    const float* A, int lda, const float* W, int ldw, const float* bias,
    float* C, int ldc, int K)
{
    tf32_gemm_body<64, 64, 2, 2, 3>(A, lda, nullptr, 1 << 30, 0, W, ldw, bias, C, ldc, K,
                                    blockIdx.x, blockIdx.y);
}

// both recurrent h-GEMMs of one GRU step in one launch (z dispatch)
__global__ __launch_bounds__(128, 4) void gru_phase1_tf32(
    const float* h0, const float* Whh0, const float* bhh0, float* gh0,
    const float* h1, const float* Whh1, const float* bhh1, float* gh1)
{
    if (blockIdx.z == 0)
        tf32_gemm_body<64, 64, 2, 2, 3>(h0, HID_, nullptr, 1 << 30, 0, Whh0, HID_, bhh0,
                                        gh0, G3_, HID_, blockIdx.x, blockIdx.y);
    else
        tf32_gemm_body<64, 64, 2, 2, 3>(h1, HID_, nullptr, 1 << 30, 0, Whh1, HID_, bhh1,
                                        gh1, G3_, HID_, blockIdx.x, blockIdx.y);
}

static const int SMEM_BIG   = 3 * (128 + 128) * LDS_ * 4;  // 110592
static const int SMEM_SMALL = 3 * (64 + 64) * LDS_ * 4;    // 55296

// ---------------- embedding + positional encoding ----------------
// faithful to reference broadcast: embedded[b,s,e] = emb[x[b,s],e] + pe[b,0,e]
__global__ void embed_kernel(const int* __restrict__ x, const float* __restrict__ emb,
                             const float* __restrict__ pe, float* __restrict__ combined)
{
    int idx = blockIdx.x * 256 + threadIdx.x;
    if (idx >= BS_ * E_) return;
    int e  = idx & (E_ - 1);
    int bs = idx >> 9;
    int b  = bs >> 7;
    combined[(size_t)bs * IN_ + e] = emb[(size_t)x[bs] * E_ + e] + pe[(size_t)b * E_ + e];
}

// ---------------- attention core: one block per (b,s) ----------------
__global__ __launch_bounds__(256) void attn_kernel(
    const float* __restrict__ q, const float* __restrict__ k, const float* __restrict__ v,
    const float* __restrict__ score_w, float* __restrict__ attn_out, float* __restrict__ ctxpre)
{
    int bs = blockIdx.x;
    int b = bs >> 7, s = bs & 127;
    __shared__ float qs[NH_][DH_];
    __shared__ float ks[NH_][DH_ + 1];
    __shared__ float vs[NH_][DH_ + 1];
    __shared__ float sq[NH_], sk[NH_];
    __shared__ float scs[NH_][NH_ + 1];
    __shared__ float es[NH_][NH_ + 1];

    int tid = threadIdx.x;
    const float* qp = q + (size_t)b * HID_;
    const float* kp = k + (size_t)bs * HID_;
    const float* vp = v + (size_t)bs * HID_;
    for (int i = tid; i < HID_; i += 256) {
        qs[i >> 6][i & 63] = qp[i];
        ks[i >> 6][i & 63] = kp[i];
        vs[i >> 6][i & 63] = vp[i];
    }
    __syncthreads();

    if (tid < 32) {
        int h = tid & 15;
        bool isq = tid < 16;
        float ssum = 0.f;
        for (int d = 0; d < DH_; ++d) { float xv = isq ? qs[h][d] : ks[h][d]; ssum += xv * xv; }
        if (isq) sq[h] = ssum; else sk[h] = ssum;
    }

    int i = tid >> 4, j = tid & 15;
    float num = 0.f;
    for (int d = 0; d < DH_; ++d) num += qs[i][d] * ks[j][d];
    __syncthreads();

    float w0, w1, w2;
    {
        float a = score_w[0], bb = score_w[1], c = score_w[2];
        float mx = fmaxf(a, fmaxf(bb, c));
        float ea = expf(a - mx), eb = expf(bb - mx), ec = expf(c - mx);
        float sm3 = ea + eb + ec;
        w0 = ea / sm3; w1 = eb / sm3; w2 = ec / sm3;
    }

    float dot = num * 0.125f;
    float denom = fmaxf(sqrtf(sq[i]) * sqrtf(sk[j]), 1e-8f);
    float cosv = num / denom;
    float d2 = sq[i] + sk[j] - 2.f * num;
    float dist = -sqrtf(fmaxf(d2, 0.f));
    float sc = w0 * dot + w1 * cosv + w2 * dist;
    scs[i][j] = sc;
    __syncthreads();

    float mx = scs[i][0];
#pragma unroll
    for (int jj = 1; jj < NH_; ++jj) mx = fmaxf(mx, scs[i][jj]);
    float ev = expf(sc - mx);
    es[i][j] = ev;
    __syncthreads();

    float ssum = 0.f;
#pragma unroll
    for (int jj = 0; jj < NH_; ++jj) ssum += es[i][jj];
    float a = ev / ssum;
    attn_out[((size_t)bs * NH_ + i) * NH_ + j] = a;
    scs[i][j] = a;
    __syncthreads();

    int i2 = tid >> 4;
    int d0 = (tid & 15) * 4;
    float o0 = 0.f, o1 = 0.f, o2 = 0.f, o3 = 0.f;
#pragma unroll
    for (int jj = 0; jj < NH_; ++jj) {
        float aij = scs[i2][jj];
        o0 += aij * vs[jj][d0 + 0];
        o1 += aij * vs[jj][d0 + 1];
        o2 += aij * vs[jj][d0 + 2];
        o3 += aij * vs[jj][d0 + 3];
    }
    int m = i2 * 8 + (s >> 4);
    size_t cbase = ((size_t)(b * 128 + m)) * HID_ + (size_t)(s & 15) * 64 + d0;
    ctxpre[cbase + 0] = o0; ctxpre[cbase + 1] = o1;
    ctxpre[cbase + 2] = o2; ctxpre[cbase + 3] = o3;
}

// ---------------- GRU elementwise gates ----------------
__device__ __forceinline__ float sigm(float x) { return 1.f / (1.f + expf(-x)); }

__global__ void gru_ew0(const float* __restrict__ gi0, const float* __restrict__ gh0,
                        float* __restrict__ h0, int t)
{
    int idx = blockIdx.x * 256 + threadIdx.x;
    int b = idx >> 10, j = idx & 1023;
    const float* gi = gi0 + (size_t)(b * S_ + t) * G3_;
    const float* gh = gh0 + (size_t)b * G3_;
    float r = sigm(gi[j] + gh[j]);
    float z = sigm(gi[HID_ + j] + gh[HID_ + j]);
    float n = tanhf(gi[2 * HID_ + j] + r * gh[2 * HID_ + j]);
    float h = h0[idx];
    h0[idx] = (1.f - z) * n + z * h;
}

__global__ void gru_ew1(const float* __restrict__ gi1, const float* __restrict__ gh1,
                        float* __restrict__ h1, float* __restrict__ rnn, int t)
{
    int idx = blockIdx.x * 256 + threadIdx.x;
    int b = idx >> 10, j = idx & 1023;
    const float* gi = gi1 + (size_t)b * G3_;
    const float* gh = gh1 + (size_t)b * G3_;
    float r = sigm(gi[j] + gh[j]);
    float z = sigm(gi[HID_ + j] + gh[HID_ + j]);
    float n = tanhf(gi[2 * HID_ + j] + r * gh[2 * HID_ + j]);
    float hn = (1.f - z) * n + z * h1[idx];
    h1[idx] = hn;
    rnn[(size_t)(b * S_ + t) * HID_ + j] = hn;
}

// ---------------- LayerNorm + ELU ----------------
__global__ __launch_bounds__(256) void ln_elu_kernel(
    const float* __restrict__ hin, const float* __restrict__ gam,
    const float* __restrict__ bet, float* __restrict__ outp)
{
    __shared__ float red[256];
    int row = blockIdx.x;
    const float* p = hin + (size_t)row * HID_;
    int t = threadIdx.x;
    float v[4];
#pragma unroll
    for (int u = 0; u < 4; ++u) v[u] = p[t + u * 256];
    float s = v[0] + v[1] + v[2] + v[3];
    red[t] = s; __syncthreads();
    for (int off = 128; off > 0; off >>= 1) { if (t < off) red[t] += red[t + off]; __syncthreads(); }
    float mean = red[0] * (1.f / HID_);
    __syncthreads();
    float sq = 0.f;
#pragma unroll
    for (int u = 0; u < 4; ++u) { float d = v[u] - mean; sq += d * d; }
    red[t] = sq; __syncthreads();
    for (int off = 128; off > 0; off >>= 1) { if (t < off) red[t] += red[t + off]; __syncthreads(); }
    float var = red[0] * (1.f / HID_);
    float inv = rsqrtf(var + 1e-5f);
#pragma unroll
    for (int u = 0; u < 4; ++u) {
        int c = t + u * 256;
        float y = (v[u] - mean) * inv * gam[c] + bet[c];
        outp[(size_t)row * HID_ + c] = (y > 0.f) ? y : expm1f(y);
    }
}

// ---------------- launch ----------------
extern "C" void kernel_launch(void* const* d_in, const int* in_sizes, int n_in,
                              void* d_out, int out_size)
{
    const int*   x      = (const int*)  d_in[0];
    const float* memory = (const float*)d_in[1];
    const float* hidden = (const float*)d_in[2];
    const float* pe     = (const float*)d_in[3];
    const float* emb    = (const float*)d_in[4];
    const float* Wq = (const float*)d_in[5];  const float* bq = (const float*)d_in[6];
    const float* Wk = (const float*)d_in[7];  const float* bk = (const float*)d_in[8];
    const float* Wv = (const float*)d_in[9];  const float* bv = (const float*)d_in[10];
    const float* Wo = (const float*)d_in[11]; const float* bo = (const float*)d_in[12];
    const float* score_w = (const float*)d_in[13];
    const float* Wih0 = (const float*)d_in[14]; const float* Whh0 = (const float*)d_in[15];
    const float* bih0 = (const float*)d_in[16]; const float* bhh0 = (const float*)d_in[17];
    const float* Wih1 = (const float*)d_in[18]; const float* Whh1 = (const float*)d_in[19];
    const float* bih1 = (const float*)d_in[20]; const float* bhh1 = (const float*)d_in[21];
    const float* W1 = (const float*)d_in[22];   const float* b1 = (const float*)d_in[23];
    const float* ln_g = (const float*)d_in[24]; const float* ln_b = (const float*)d_in[25];
    const float* W2 = (const float*)d_in[26];   const float* b2 = (const float*)d_in[27];

    float* out        = (float*)d_out;
    float* out_logits = out;
    float* out_attn   = out + (size_t)BS_ * V_;
    float* out_hidden = out_attn + (size_t)BS_ * NH_ * NH_;

    float *combined, *qb, *kb, *vb, *ctxpre, *gi0, *h0, *h1, *gh0, *gh1, *gi1, *rnn, *lin1, *act;
    cudaGetSymbolAddress((void**)&combined, g_combined);
    cudaGetSymbolAddress((void**)&qb, g_q);
    cudaGetSymbolAddress((void**)&kb, g_k);
    cudaGetSymbolAddress((void**)&vb, g_v);
    cudaGetSymbolAddress((void**)&ctxpre, g_ctxpre);
    cudaGetSymbolAddress((void**)&gi0, g_gi0);
    cudaGetSymbolAddress((void**)&h0, g_h0);
    cudaGetSymbolAddress((void**)&h1, g_h1);
    cudaGetSymbolAddress((void**)&gh0, g_gh0);
    cudaGetSymbolAddress((void**)&gh1, g_gh1);
    cudaGetSymbolAddress((void**)&gi1, g_gi1);
    cudaGetSymbolAddress((void**)&rnn, g_rnn);
    cudaGetSymbolAddress((void**)&lin1, g_lin1);
    cudaGetSymbolAddress((void**)&act, g_act);

    // idempotent, host-side, capture-legal; no static guards (contract requirement)
    cudaFuncSetAttribute(tf32_gemm_big,   cudaFuncAttributeMaxDynamicSharedMemorySize, SMEM_BIG);
    cudaFuncSetAttribute(tf32_gemm_small, cudaFuncAttributeMaxDynamicSharedMemorySize, SMEM_SMALL);
    cudaFuncSetAttribute(gru_phase1_tf32, cudaFuncAttributeMaxDynamicSharedMemorySize, SMEM_SMALL);

    const int NOK = 1 << 30;

    // 1) embedded -> combined[:, :, 0:512]
    embed_kernel<<<(BS_ * E_ + 255) / 256, 256>>>(x, emb, pe, combined);

    // 2) q = hidden[1] @ Wq^T + bq
    tf32_gemm_big<<<dim3(HID_ / 128, B_ / 128), 256, SMEM_BIG>>>(
        hidden + (size_t)B_ * HID_, HID_, nullptr, NOK, 0, Wq, HID_, bq, qb, HID_, HID_);

    // 3) k, v projections
    tf32_gemm_big<<<dim3(HID_ / 128, BS_ / 128), 256, SMEM_BIG>>>(
        memory, HID_, nullptr, NOK, 0, Wk, HID_, bk, kb, HID_, HID_);
    tf32_gemm_big<<<dim3(HID_ / 128, BS_ / 128), 256, SMEM_BIG>>>(
        memory, HID_, nullptr, NOK, 0, Wv, HID_, bv, vb, HID_, HID_);

    // 4) attention core (also writes attn_w output)
    attn_kernel<<<BS_, 256>>>(qb, kb, vb, score_w, out_attn, ctxpre);

    // 5) context = ctxpre @ Wo^T + bo  -> combined[:, :, 512:1536]
    tf32_gemm_big<<<dim3(HID_ / 128, BS_ / 128), 256, SMEM_BIG>>>(
        ctxpre, HID_, nullptr, NOK, 0, Wo, HID_, bo, combined + E_, IN_, HID_);

    // 6) gi0 = combined @ Wih0^T + bih0
    tf32_gemm_big<<<dim3(G3_ / 128, BS_ / 128), 256, SMEM_BIG>>>(
        combined, IN_, nullptr, NOK, 0, Wih0, IN_, bih0, gi0, G3_, IN_);

    // 7) init GRU states
    cudaMemcpyToSymbolAsync(g_h0, hidden, (size_t)B_ * HID_ * sizeof(float), 0,
                            cudaMemcpyDeviceToDevice, 0);
    cudaMemcpyToSymbolAsync(g_h1, hidden + (size_t)B_ * HID_, (size_t)B_ * HID_ * sizeof(float), 0,
                            cudaMemcpyDeviceToDevice, 0);

    // 8) GRU recurrence
    for (int t = 0; t < S_; ++t) {
        gru_phase1_tf32<<<dim3(G3_ / 64, B_ / 64, 2), 128, SMEM_SMALL>>>(
            h0, Whh0, bhh0, gh0, h1, Whh1, bhh1, gh1);
        gru_ew0<<<(B_ * HID_) / 256, 256>>>(gi0, gh0, h0, t);
        tf32_gemm_small<<<dim3(G3_ / 64, B_ / 64), 128, SMEM_SMALL>>>(
            h0, HID_, Wih1, HID_, bih1, gi1, G3_, HID_);
        gru_ew1<<<(B_ * HID_) / 256, 256>>>(gi1, gh1, h1, rnn, t);
    }

    // 9) new_hidden output
    cudaMemcpyFromSymbolAsync(out_hidden, g_h0, (size_t)B_ * HID_ * sizeof(float), 0,
                              cudaMemcpyDeviceToDevice, 0);
    cudaMemcpyFromSymbolAsync(out_hidden + (size_t)B_ * HID_, g_h1,
                              (size_t)B_ * HID_ * sizeof(float), 0, cudaMemcpyDeviceToDevice, 0);

    // 10) h = concat(rnn_out, context) @ W1^T + b1
    tf32_gemm_big<<<dim3(HID_ / 128, BS_ / 128), 256, SMEM_BIG>>>(
        rnn, HID_, combined + E_, HID_, IN_, W1, 2 * HID_, b1, lin1, HID_, 2 * HID_);

    // 11) LayerNorm + ELU
    ln_elu_kernel<<<BS_, 256>>>(lin1, ln_g, ln_b, act);

    // 12) logits = act @ W2^T + b2
    tf32_gemm_big<<<dim3(V_ / 128, BS_ / 128), 256, SMEM_BIG>>>(
        act, HID_, nullptr, NOK, 0, W2, HID_, b2, out_logits, V_, HID_);
}

// round 8
// speedup vs baseline: 3.3411x; 1.0699x over previous
#include <cuda_runtime.h>
#include <math.h>
#include <stdint.h>

#define B_    128
#define S_    128
#define E_    512
#define HID_  1024
#define NH_   16
#define DH_   64
#define V_    8192
#define IN_   1536
#define G3_   3072
#define BS_   (B_*S_)   // 16384

// ---------------- scratch (device globals; no allocation allowed) ----------------
__device__ float g_combined[(size_t)BS_*IN_];   // rounded at producer
__device__ float g_q[(size_t)B_*HID_];
__device__ float g_k[(size_t)BS_*HID_];
__device__ float g_v[(size_t)BS_*HID_];
__device__ float g_ctxpre[(size_t)BS_*HID_];    // rounded at producer
__device__ float g_gi0[(size_t)BS_*G3_];
__device__ float g_h0[(size_t)B_*HID_];
__device__ float g_h1[(size_t)B_*HID_];
__device__ float g_gh0[(size_t)B_*G3_];
__device__ float g_gh1[(size_t)B_*G3_];
__device__ float g_gi1[(size_t)B_*G3_];
__device__ float g_rnn[(size_t)BS_*HID_];       // rounded at producer
__device__ float g_lin1[(size_t)BS_*HID_];
__device__ float g_act[(size_t)BS_*HID_];       // rounded at producer

// pre-rounded (tf32) copies of pure-input GEMM operands
__device__ float r_Wq[(size_t)HID_*HID_];
__device__ float r_Wk[(size_t)HID_*HID_];
__device__ float r_Wv[(size_t)HID_*HID_];
__device__ float r_Wo[(size_t)HID_*HID_];
__device__ float r_Wih0[(size_t)G3_*IN_];
__device__ float r_Whh0[(size_t)G3_*HID_];
__device__ float r_Wih1[(size_t)G3_*HID_];
__device__ float r_Whh1[(size_t)G3_*HID_];
__device__ float r_W1[(size_t)HID_*2*HID_];
__device__ float r_W2[(size_t)V_*HID_];
__device__ float r_mem[(size_t)BS_*HID_];
__device__ float r_hid[(size_t)B_*HID_];

// ================= tf32 tensor-core GEMM =================
__device__ __forceinline__ void cp16(uint32_t s, const void* g) {
    asm volatile("cp.async.cg.shared.global [%0], [%1], 16;" :: "r"(s), "l"(g));
}
__device__ __forceinline__ void cp_commit() { asm volatile("cp.async.commit_group;"); }
template<int N> __device__ __forceinline__ void cp_wait() {
    asm volatile("cp.async.wait_group %0;" :: "n"(N));
}
__device__ __forceinline__ uint32_t f2tf32(float x) {
    uint32_t r; asm("cvt.rna.tf32.f32 %0, %1;" : "=r"(r) : "f"(x)); return r;
}
__device__ __forceinline__ float roundtf(float x) { return __uint_as_float(f2tf32(x)); }
__device__ __forceinline__ void mma_tf32(float* c, const uint32_t* a, const uint32_t* b) {
    asm volatile("mma.sync.aligned.m16n8k8.row.col.f32.tf32.tf32.f32 "
                 "{%0,%1,%2,%3}, {%4,%5,%6,%7}, {%8,%9}, {%0,%1,%2,%3};"
                 : "+f"(c[0]), "+f"(c[1]), "+f"(c[2]), "+f"(c[3])
                 : "r"(a[0]), "r"(a[1]), "r"(a[2]), "r"(a[3]), "r"(b[0]), "r"(b[1]));
}

#define BK_   32
#define LDS_  36   // BK + 4 pad; conflict-free fragment loads

// CVTA: convert A fragments (A not pre-rounded). B (weights) always pre-rounded.
template<int BM, int BN, int WM, int WN, int STAGES, bool CVTA>
__device__ __forceinline__ void tf32_gemm_body(
    const float* __restrict__ A, int lda,
    const float* __restrict__ A2, int ksplit, int lda2,
    const float* __restrict__ W, int ldw,
    const float* __restrict__ bias,
    float* __restrict__ C, int ldc, int K,
    int bxi, int byi, bool roundC)
{
    extern __shared__ float sm[];
    constexpr int THREADS = WM * WN * 32;
    constexpr int WTM = BM / WM;
    constexpr int WTN = BN / WN;
    constexpr int MT  = WTM / 16;
    constexpr int NT  = WTN / 8;

    float* As = sm;
    float* Bs = sm + (size_t)STAGES * BM * LDS_;

    const int tid = threadIdx.x;
    const int bm = byi * BM;
    const int bn = bxi * BN;

    const int warp = tid >> 5, lane = tid & 31;
    const int wm = warp / WN, wn = warp % WN;
    const int g = lane >> 2, tg = lane & 3;

    float acc[MT][NT][4];
#pragma unroll
    for (int i = 0; i < MT; ++i)
#pragma unroll
        for (int j = 0; j < NT; ++j) {
            acc[i][j][0] = 0.f; acc[i][j][1] = 0.f; acc[i][j][2] = 0.f; acc[i][j][3] = 0.f;
        }

    auto load_stage = [&](int stage, int k0) {
        const float* Ab; int alda, koff;
        if (A2 != nullptr && k0 >= ksplit) { Ab = A2; alda = lda2; koff = k0 - ksplit; }
        else { Ab = A; alda = lda; koff = k0; }
        constexpr int A4 = BM * 8;
#pragma unroll
        for (int i = tid; i < A4; i += THREADS) {
            int row = i >> 3, c4 = (i & 7) * 4;
            const float* gp = Ab + (size_t)(bm + row) * alda + koff + c4;
            uint32_t s = (uint32_t)__cvta_generic_to_shared(As + (size_t)stage * BM * LDS_ + row * LDS_ + c4);
            cp16(s, gp);
        }
        constexpr int B4 = BN * 8;
#pragma unroll
        for (int i = tid; i < B4; i += THREADS) {
            int row = i >> 3, c4 = (i & 7) * 4;
            const float* gp = W + (size_t)(bn + row) * ldw + k0 + c4;
            uint32_t s = (uint32_t)__cvta_generic_to_shared(Bs + (size_t)stage * BN * LDS_ + row * LDS_ + c4);
            cp16(s, gp);
        }
        cp_commit();
    };

    const int nk = K / BK_;
#pragma unroll
    for (int s = 0; s < STAGES - 1; ++s) load_stage(s, s * BK_);

    for (int c = 0; c < nk; ++c) {
        cp_wait<STAGES - 2>();
        __syncthreads();
        if (c + STAGES - 1 < nk) load_stage((c + STAGES - 1) % STAGES, (c + STAGES - 1) * BK_);
        else cp_commit();

        const float* Ap = As + (size_t)(c % STAGES) * BM * LDS_;
        const float* Bp = Bs + (size_t)(c % STAGES) * BN * LDS_;
#pragma unroll
        for (int kk = 0; kk < BK_ / 8; ++kk) {
            const int k8 = kk * 8;
            uint32_t ua[MT][4], ub[NT][2];
#pragma unroll
            for (int mt = 0; mt < MT; ++mt) {
                int r0 = wm * WTM + mt * 16 + g;
                float a0 = Ap[r0 * LDS_ + k8 + tg];
                float a1 = Ap[(r0 + 8) * LDS_ + k8 + tg];
                float a2 = Ap[r0 * LDS_ + k8 + tg + 4];
                float a3 = Ap[(r0 + 8) * LDS_ + k8 + tg + 4];
                if (CVTA) {
                    ua[mt][0] = f2tf32(a0); ua[mt][1] = f2tf32(a1);
                    ua[mt][2] = f2tf32(a2); ua[mt][3] = f2tf32(a3);
                } else {
                    ua[mt][0] = __float_as_uint(a0); ua[mt][1] = __float_as_uint(a1);
                    ua[mt][2] = __float_as_uint(a2); ua[mt][3] = __float_as_uint(a3);
                }
            }
#pragma unroll
            for (int nt = 0; nt < NT; ++nt) {
                int c0 = wn * WTN + nt * 8 + g;
                ub[nt][0] = __float_as_uint(Bp[c0 * LDS_ + k8 + tg]);
                ub[nt][1] = __float_as_uint(Bp[c0 * LDS_ + k8 + tg + 4]);
            }
#pragma unroll
            for (int mt = 0; mt < MT; ++mt)
#pragma unroll
                for (int nt = 0; nt < NT; ++nt)
                    mma_tf32(acc[mt][nt], ua[mt], ub[nt]);
        }
    }

    // epilogue
#pragma unroll
    for (int mt = 0; mt < MT; ++mt) {
        int row0 = bm + wm * WTM + mt * 16 + g;
#pragma unroll
        for (int nt = 0; nt < NT; ++nt) {
            int col = bn + wn * WTN + nt * 8 + 2 * tg;
            float b0 = bias[col], b1 = bias[col + 1];
            float x0 = acc[mt][nt][0] + b0, x1 = acc[mt][nt][1] + b1;
            float x2 = acc[mt][nt][2] + b0, x3 = acc[mt][nt][3] + b1;
            if (roundC) { x0 = roundtf(x0); x1 = roundtf(x1); x2 = roundtf(x2); x3 = roundtf(x3); }
            *(float2*)(C + (size_t)row0 * ldc + col) = make_float2(x0, x1);
            *(float2*)(C + (size_t)(row0 + 8) * ldc + col) = make_float2(x2, x3);
        }
    }
}

// big: 128x128 tiles, 8 warps, warp tile 32x64 (WM=4, WN=2), 3 stages, A pre-rounded.
__global__ __launch_bounds__(256, 2) void tf32_gemm_big(
    const float* A, int lda, const float* A2, int ksplit, int lda2,
    const float* W, int ldw, const float* bias, float* C, int ldc, int K, int roundC)
{
    tf32_gemm_body<128, 128, 4, 2, 3, false>(A, lda, A2, ksplit, lda2, W, ldw, bias, C, ldc, K,
                                             blockIdx.x, blockIdx.y, roundC != 0);
}

// small: 64x64 tiles, 4 warps, warp tile 32x32, 3 stages, A converted in-loop (h exact).
__global__ __launch_bounds__(128, 4) void tf32_gemm_small(
    const float* A, int lda, const float* W, int ldw, const float* bias,
    float* C, int ldc, int K)
{
    tf32_gemm_body<64, 64, 2, 2, 3, true>(A, lda, nullptr, 1 << 30, 0, W, ldw, bias, C, ldc, K,
                                          blockIdx.x, blockIdx.y, false);
}

__global__ __launch_bounds__(128, 4) void gru_phase1_tf32(
    const float* h0, const float* Whh0, const float* bhh0, float* gh0,
    const float* h1, const float* Whh1, const float* bhh1, float* gh1)
{
    if (blockIdx.z == 0)
        tf32_gemm_body<64, 64, 2, 2, 3, true>(h0, HID_, nullptr, 1 << 30, 0, Whh0, HID_, bhh0,
                                              gh0, G3_, HID_, blockIdx.x, blockIdx.y, false);
    else
        tf32_gemm_body<64, 64, 2, 2, 3, true>(h1, HID_, nullptr, 1 << 30, 0, Whh1, HID_, bhh1,
                                              gh1, G3_, HID_, blockIdx.x, blockIdx.y, false);
}

static const int SMEM_BIG   = 3 * (128 + 128) * LDS_ * 4;  // 110592
static const int SMEM_SMALL = 3 * (64 + 64) * LDS_ * 4;    // 55296

// ---------------- tf32 pre-rounding pass ----------------
__global__ void round_tf32_kernel(const float* __restrict__ in, float* __restrict__ out, int n4)
{
    int i = blockIdx.x * 256 + threadIdx.x;
    if (i >= n4) return;
    float4 v = ((const float4*)in)[i];
    v.x = __uint_as_float(f2tf32(v.x));
    v.y = __uint_as_float(f2tf32(v.y));
    v.z = __uint_as_float(f2tf32(v.z));
    v.w = __uint_as_float(f2tf32(v.w));
    ((float4*)out)[i] = v;
}

// ---------------- embedding + positional encoding (rounded store) ----------------
__global__ void embed_kernel(const int* __restrict__ x, const float* __restrict__ emb,
                             const float* __restrict__ pe, float* __restrict__ combined)
{
    int idx = blockIdx.x * 256 + threadIdx.x;
    if (idx >= BS_ * E_) return;
    int e  = idx & (E_ - 1);
    int bs = idx >> 9;
    int b  = bs >> 7;
    combined[(size_t)bs * IN_ + e] = roundtf(emb[(size_t)x[bs] * E_ + e] + pe[(size_t)b * E_ + e]);
}

// ---------------- attention core ----------------
__global__ __launch_bounds__(256) void attn_kernel(
    const float* __restrict__ q, const float* __restrict__ k, const float* __restrict__ v,
    const float* __restrict__ score_w, float* __restrict__ attn_out, float* __restrict__ ctxpre)
{
    int bs = blockIdx.x;
    int b = bs >> 7, s = bs & 127;
    __shared__ float qs[NH_][DH_];
    __shared__ float ks[NH_][DH_ + 1];
    __shared__ float vs[NH_][DH_ + 1];
    __shared__ float sq[NH_], sk[NH_];
    __shared__ float scs[NH_][NH_ + 1];
    __shared__ float es[NH_][NH_ + 1];

    int tid = threadIdx.x;
    const float* qp = q + (size_t)b * HID_;
    const float* kp = k + (size_t)bs * HID_;
    const float* vp = v + (size_t)bs * HID_;
    for (int i = tid; i < HID_; i += 256) {
        qs[i >> 6][i & 63] = qp[i];
        ks[i >> 6][i & 63] = kp[i];
        vs[i >> 6][i & 63] = vp[i];
    }
    __syncthreads();

    if (tid < 32) {
        int h = tid & 15;
        bool isq = tid < 16;
        float ssum = 0.f;
        for (int d = 0; d < DH_; ++d) { float xv = isq ? qs[h][d] : ks[h][d]; ssum += xv * xv; }
        if (isq) sq[h] = ssum; else sk[h] = ssum;
    }

    int i = tid >> 4, j = tid & 15;
    float num = 0.f;
    for (int d = 0; d < DH_; ++d) num += qs[i][d] * ks[j][d];
    __syncthreads();

    float w0, w1, w2;
    {
        float a = score_w[0], bb = score_w[1], c = score_w[2];
        float mx = fmaxf(a, fmaxf(bb, c));
        float ea = expf(a - mx), eb = expf(bb - mx), ec = expf(c - mx);
        float sm3 = ea + eb + ec;
        w0 = ea / sm3; w1 = eb / sm3; w2 = ec / sm3;
    }

    float dot = num * 0.125f;
    float denom = fmaxf(sqrtf(sq[i]) * sqrtf(sk[j]), 1e-8f);
    float cosv = num / denom;
    float d2 = sq[i] + sk[j] - 2.f * num;
    float dist = -sqrtf(fmaxf(d2, 0.f));
    float sc = w0 * dot + w1 * cosv + w2 * dist;
    scs[i][j] = sc;
    __syncthreads();

    float mx = scs[i][0];
#pragma unroll
    for (int jj = 1; jj < NH_; ++jj) mx = fmaxf(mx, scs[i][jj]);
    float ev = expf(sc - mx);
    es[i][j] = ev;
    __syncthreads();

    float ssum = 0.f;
#pragma unroll
    for (int jj = 0; jj < NH_; ++jj) ssum += es[i][jj];
    float a = ev / ssum;
    attn_out[((size_t)bs * NH_ + i) * NH_ + j] = a;
    scs[i][j] = a;
    __syncthreads();

    int i2 = tid >> 4;
    int d0 = (tid & 15) * 4;
    float o0 = 0.f, o1 = 0.f, o2 = 0.f, o3 = 0.f;
#pragma unroll
    for (int jj = 0; jj < NH_; ++jj) {
        float aij = scs[i2][jj];
        o0 += aij * vs[jj][d0 + 0];
        o1 += aij * vs[jj][d0 + 1];
        o2 += aij * vs[jj][d0 + 2];
        o3 += aij * vs[jj][d0 + 3];
    }
    int m = i2 * 8 + (s >> 4);
    size_t cbase = ((size_t)(b * 128 + m)) * HID_ + (size_t)(s & 15) * 64 + d0;
    ctxpre[cbase + 0] = roundtf(o0); ctxpre[cbase + 1] = roundtf(o1);
    ctxpre[cbase + 2] = roundtf(o2); ctxpre[cbase + 3] = roundtf(o3);
}

// ---------------- GRU elementwise gates ----------------
__device__ __forceinline__ float sigm(float x) { return 1.f / (1.f + expf(-x)); }

__global__ void gru_ew0(const float* __restrict__ gi0, const float* __restrict__ gh0,
                        float* __restrict__ h0, int t)
{
    int idx = blockIdx.x * 256 + threadIdx.x;
    int b = idx >> 10, j = idx & 1023;
    const float* gi = gi0 + (size_t)(b * S_ + t) * G3_;
    const float* gh = gh0 + (size_t)b * G3_;
    float r = sigm(gi[j] + gh[j]);
    float z = sigm(gi[HID_ + j] + gh[HID_ + j]);
    float n = tanhf(gi[2 * HID_ + j] + r * gh[2 * HID_ + j]);
    float h = h0[idx];
    h0[idx] = (1.f - z) * n + z * h;
}

__global__ void gru_ew1(const float* __restrict__ gi1, const float* __restrict__ gh1,
                        float* __restrict__ h1, float* __restrict__ rnn, int t)
{
    int idx = blockIdx.x * 256 + threadIdx.x;
    int b = idx >> 10, j = idx & 1023;
    const float* gi = gi1 + (size_t)b * G3_;
    const float* gh = gh1 + (size_t)b * G3_;
    float r = sigm(gi[j] + gh[j]);
    float z = sigm(gi[HID_ + j] + gh[HID_ + j]);
    float n = tanhf(gi[2 * HID_ + j] + r * gh[2 * HID_ + j]);
    float hn = (1.f - z) * n + z * h1[idx];
    h1[idx] = hn;
    rnn[(size_t)(b * S_ + t) * HID_ + j] = roundtf(hn);   // rnn only feeds the W1 GEMM
}

// ---------------- LayerNorm + ELU (rounded store; act only feeds W2 GEMM) ---------
__global__ __launch_bounds__(256) void ln_elu_kernel(
    const float* __restrict__ hin, const float* __restrict__ gam,
    const float* __restrict__ bet, float* __restrict__ outp)
{
    __shared__ float red[256];
    int row = blockIdx.x;
    const float* p = hin + (size_t)row * HID_;
    int t = threadIdx.x;
    float v[4];
#pragma unroll
    for (int u = 0; u < 4; ++u) v[u] = p[t + u * 256];
    float s = v[0] + v[1] + v[2] + v[3];
    red[t] = s; __syncthreads();
    for (int off = 128; off > 0; off >>= 1) { if (t < off) red[t] += red[t + off]; __syncthreads(); }
    float mean = red[0] * (1.f / HID_);
    __syncthreads();
    float sq = 0.f;
#pragma unroll
    for (int u = 0; u < 4; ++u) { float d = v[u] - mean; sq += d * d; }
    red[t] = sq; __syncthreads();
    for (int off = 128; off > 0; off >>= 1) { if (t < off) red[t] += red[t + off]; __syncthreads(); }
    float var = red[0] * (1.f / HID_);
    float inv = rsqrtf(var + 1e-5f);
#pragma unroll
    for (int u = 0; u < 4; ++u) {
        int c = t + u * 256;
        float y = (v[u] - mean) * inv * gam[c] + bet[c];
        outp[(size_t)row * HID_ + c] = roundtf((y > 0.f) ? y : expm1f(y));
    }
}

// ---------------- launch ----------------
extern "C" void kernel_launch(void* const* d_in, const int* in_sizes, int n_in,
                              void* d_out, int out_size)
{
    const int*   x      = (const int*)  d_in[0];
    const float* memory = (const float*)d_in[1];
    const float* hidden = (const float*)d_in[2];
    const float* pe     = (const float*)d_in[3];
    const float* emb    = (const float*)d_in[4];
    const float* Wq = (const float*)d_in[5];  const float* bq = (const float*)d_in[6];
    const float* Wk = (const float*)d_in[7];  const float* bk = (const float*)d_in[8];
    const float* Wv = (const float*)d_in[9];  const float* bv = (const float*)d_in[10];
    const float* Wo = (const float*)d_in[11]; const float* bo = (const float*)d_in[12];
    const float* score_w = (const float*)d_in[13];
    const float* Wih0 = (const float*)d_in[14]; const float* Whh0 = (const float*)d_in[15];
    const float* bih0 = (const float*)d_in[16]; const float* bhh0 = (const float*)d_in[17];
    const float* Wih1 = (const float*)d_in[18]; const float* Whh1 = (const float*)d_in[19];
    const float* bih1 = (const float*)d_in[20]; const float* bhh1 = (const float*)d_in[21];
    const float* W1 = (const float*)d_in[22];   const float* b1 = (const float*)d_in[23];
    const float* ln_g = (const float*)d_in[24]; const float* ln_b = (const float*)d_in[25];
    const float* W2 = (const float*)d_in[26];   const float* b2 = (const float*)d_in[27];

    float* out        = (float*)d_out;
    float* out_logits = out;
    float* out_attn   = out + (size_t)BS_ * V_;
    float* out_hidden = out_attn + (size_t)BS_ * NH_ * NH_;

    float *combined, *qb, *kb, *vb, *ctxpre, *gi0, *h0, *h1, *gh0, *gh1, *gi1, *rnn, *lin1, *act;
    float *pWq, *pWk, *pWv, *pWo, *pWih0, *pWhh0, *pWih1, *pWhh1, *pW1, *pW2, *pmem, *phid;
    cudaGetSymbolAddress((void**)&combined, g_combined);
    cudaGetSymbolAddress((void**)&qb, g_q);
    cudaGetSymbolAddress((void**)&kb, g_k);
    cudaGetSymbolAddress((void**)&vb, g_v);
    cudaGetSymbolAddress((void**)&ctxpre, g_ctxpre);
    cudaGetSymbolAddress((void**)&gi0, g_gi0);
    cudaGetSymbolAddress((void**)&h0, g_h0);
    cudaGetSymbolAddress((void**)&h1, g_h1);
    cudaGetSymbolAddress((void**)&gh0, g_gh0);
    cudaGetSymbolAddress((void**)&gh1, g_gh1);
    cudaGetSymbolAddress((void**)&gi1, g_gi1);
    cudaGetSymbolAddress((void**)&rnn, g_rnn);
    cudaGetSymbolAddress((void**)&lin1, g_lin1);
    cudaGetSymbolAddress((void**)&act, g_act);
    cudaGetSymbolAddress((void**)&pWq, r_Wq);
    cudaGetSymbolAddress((void**)&pWk, r_Wk);
    cudaGetSymbolAddress((void**)&pWv, r_Wv);
    cudaGetSymbolAddress((void**)&pWo, r_Wo);
    cudaGetSymbolAddress((void**)&pWih0, r_Wih0);
    cudaGetSymbolAddress((void**)&pWhh0, r_Whh0);
    cudaGetSymbolAddress((void**)&pWih1, r_Wih1);
    cudaGetSymbolAddress((void**)&pWhh1, r_Whh1);
    cudaGetSymbolAddress((void**)&pW1, r_W1);
    cudaGetSymbolAddress((void**)&pW2, r_W2);
    cudaGetSymbolAddress((void**)&pmem, r_mem);
    cudaGetSymbolAddress((void**)&phid, r_hid);

    cudaFuncSetAttribute(tf32_gemm_big,   cudaFuncAttributeMaxDynamicSharedMemorySize, SMEM_BIG);
    cudaFuncSetAttribute(tf32_gemm_small, cudaFuncAttributeMaxDynamicSharedMemorySize, SMEM_SMALL);
    cudaFuncSetAttribute(gru_phase1_tf32, cudaFuncAttributeMaxDynamicSharedMemorySize, SMEM_SMALL);

    const int NOK = 1 << 30;

    // 0) pre-round pure-input GEMM operands to tf32 (bit-identical to in-loop cvt)
    auto rnd = [](const float* src, float* dst, size_t n) {
        int n4 = (int)(n / 4);
        round_tf32_kernel<<<(n4 + 255) / 256, 256>>>(src, dst, n4);
    };
    rnd(Wq, pWq, (size_t)HID_ * HID_);
    rnd(Wk, pWk, (size_t)HID_ * HID_);
    rnd(Wv, pWv, (size_t)HID_ * HID_);
    rnd(Wo, pWo, (size_t)HID_ * HID_);
    rnd(Wih0, pWih0, (size_t)G3_ * IN_);
    rnd(Whh0, pWhh0, (size_t)G3_ * HID_);
    rnd(Wih1, pWih1, (size_t)G3_ * HID_);
    rnd(Whh1, pWhh1, (size_t)G3_ * HID_);
    rnd(W1, pW1, (size_t)HID_ * 2 * HID_);
    rnd(W2, pW2, (size_t)V_ * HID_);
    rnd(memory, pmem, (size_t)BS_ * HID_);
    rnd(hidden + (size_t)B_ * HID_, phid, (size_t)B_ * HID_);

    // 1) embedded -> combined[:, :, 0:512] (rounded)
    embed_kernel<<<(BS_ * E_ + 255) / 256, 256>>>(x, emb, pe, combined);

    // 2) q = hidden[1] @ Wq^T + bq
    tf32_gemm_big<<<dim3(HID_ / 128, B_ / 128), 256, SMEM_BIG>>>(
        phid, HID_, nullptr, NOK, 0, pWq, HID_, bq, qb, HID_, HID_, 0);

    // 3) k, v projections
    tf32_gemm_big<<<dim3(HID_ / 128, BS_ / 128), 256, SMEM_BIG>>>(
        pmem, HID_, nullptr, NOK, 0, pWk, HID_, bk, kb, HID_, HID_, 0);
    tf32_gemm_big<<<dim3(HID_ / 128, BS_ / 128), 256, SMEM_BIG>>>(
        pmem, HID_, nullptr, NOK, 0, pWv, HID_, bv, vb, HID_, HID_, 0);

    // 4) attention core (writes attn_w exact; ctxpre rounded)
    attn_kernel<<<BS_, 256>>>(qb, kb, vb, score_w, out_attn, ctxpre);

    // 5) context = ctxpre @ Wo^T + bo -> combined[:, :, 512:1536] (rounded store)
    tf32_gemm_big<<<dim3(HID_ / 128, BS_ / 128), 256, SMEM_BIG>>>(
        ctxpre, HID_, nullptr, NOK, 0, pWo, HID_, bo, combined + E_, IN_, HID_, 1);

    // 6) gi0 = combined @ Wih0^T + bih0 (output exact fp32 — feeds gates)
    tf32_gemm_big<<<dim3(G3_ / 128, BS_ / 128), 256, SMEM_BIG>>>(
        combined, IN_, nullptr, NOK, 0, pWih0, IN_, bih0, gi0, G3_, IN_, 0);

    // 7) init GRU states (exact)
    cudaMemcpyToSymbolAsync(g_h0, hidden, (size_t)B_ * HID_ * sizeof(float), 0,
                            cudaMemcpyDeviceToDevice, 0);
    cudaMemcpyToSymbolAsync(g_h1, hidden + (size_t)B_ * HID_, (size_t)B_ * HID_ * sizeof(float), 0,
                            cudaMemcpyDeviceToDevice, 0);

    // 8) GRU recurrence
    for (int t = 0; t < S_; ++t) {
        gru_phase1_tf32<<<dim3(G3_ / 64, B_ / 64, 2), 128, SMEM_SMALL>>>(
            h0, pWhh0, bhh0, gh0, h1, pWhh1, bhh1, gh1);
        gru_ew0<<<(B_ * HID_) / 256, 256>>>(gi0, gh0, h0, t);
        tf32_gemm_small<<<dim3(G3_ / 64, B_ / 64), 128, SMEM_SMALL>>>(
            h0, HID_, pWih1, HID_, bih1, gi1, G3_, HID_);
        gru_ew1<<<(B_ * HID_) / 256, 256>>>(gi1, gh1, h1, rnn, t);
    }

    // 9) new_hidden output
    cudaMemcpyFromSymbolAsync(out_hidden, g_h0, (size_t)B_ * HID_ * sizeof(float), 0,
                              cudaMemcpyDeviceToDevice, 0);
    cudaMemcpyFromSymbolAsync(out_hidden + (size_t)B_ * HID_, g_h1,
                              (size_t)B_ * HID_ * sizeof(float), 0, cudaMemcpyDeviceToDevice, 0);

    // 10) h = concat(rnn_out, context) @ W1^T + b1 (A pre-rounded at producers)
    tf32_gemm_big<<<dim3(HID_ / 128, BS_ / 128), 256, SMEM_BIG>>>(
        rnn, HID_, combined + E_, HID_, IN_, pW1, 2 * HID_, b1, lin1, HID_, 2 * HID_, 0);

    // 11) LayerNorm + ELU (rounded store)
    ln_elu_kernel<<<BS_, 256>>>(lin1, ln_g, ln_b, act);

    // 12) logits = act @ W2^T + b2
    tf32_gemm_big<<<dim3(V_ / 128, BS_ / 128), 256, SMEM_BIG>>>(
        act, HID_, nullptr, NOK, 0, pW2, HID_, b2, out_logits, V_, HID_, 0);
}